// round 10
// baseline (speedup 1.0000x reference)
#include <cuda_runtime.h>
#include <cstdint>

// Problem constants (fixed by the reference: B=64, S=512, H=768)
#define PB 64
#define PS 512
#define PH 768
#define NTOK (PB * PS)                       // 32768 tokens
#define SPAN ((size_t)PB * PS * PS)          // 16,777,216 elements per output tensor

// Per-token scratch (device globals: allocation-free, graph-capturable)
__device__ float         g_a[NTOK];
__device__ float         g_c[NTOK];
__device__ unsigned char g_sc[NTOK];
__device__ unsigned char g_ec[NTOK];

// ---------------------------------------------------------------------------
// Kernel 1: per-token fused matvecs, 4 TOKENS PER WARP.
// ncu (R9): token kernel is L1/LSU-bound (L1=74.3%, DRAM=43%). Dominant cost
// was 24 LDS.128/token (12 KB weights re-read per token). Sharing each weight
// LDS across 4 tokens cuts smem phases 96->24 per token; the rolled k-loop
// (#pragma unroll 1) keeps live registers bounded (the fully-unrolled 2-token
// variant R5 regressed on register pressure). Merged pair-reduction cuts
// shuffles 20->6 per token.
// ---------------------------------------------------------------------------
__global__ __launch_bounds__(256) void token_kernel(
    const float* __restrict__ rep,
    const int*   __restrict__ mask,
    const float* __restrict__ W_start,
    const float* __restrict__ b_start,
    const float* __restrict__ W_end,
    const float* __restrict__ b_end,
    const float* __restrict__ W_m,
    const float* __restrict__ b_m)
{
    __shared__ float4 sw[4][PH / 4];   // 12 KB: 4 combined weight vectors

    const int tid = threadIdx.x;

    // Stage combined weights into shared (once per block)
    for (int i = tid; i < PH; i += blockDim.x) {
        reinterpret_cast<float*>(sw[0])[i] = W_start[i * 2 + 1] - W_start[i * 2 + 0];
        reinterpret_cast<float*>(sw[1])[i] = W_end[i * 2 + 1]   - W_end[i * 2 + 0];
        reinterpret_cast<float*>(sw[2])[i] = W_m[i];
        reinterpret_cast<float*>(sw[3])[i] = W_m[PH + i];
    }
    __syncthreads();

    const int warp = tid >> 5;
    const int lane = tid & 31;
    const int t0   = (blockIdx.x * 8 + warp) * 4;     // 4 consecutive tokens

    const float bsd = b_start[1] - b_start[0];
    const float bed = b_end[1]   - b_end[0];
    const float bm  = b_m[0];

    const float4* r4 = reinterpret_cast<const float4*>(rep) + (size_t)t0 * (PH / 4);

    float accd[4] = {0.f, 0.f, 0.f, 0.f};   // start-diff per token
    float acce[4] = {0.f, 0.f, 0.f, 0.f};   // end-diff
    float acca[4] = {0.f, 0.f, 0.f, 0.f};   // a = rep.W_m[:H]
    float accc[4] = {0.f, 0.f, 0.f, 0.f};   // c = rep.W_m[H:]

    #pragma unroll 1
    for (int k = 0; k < PH / 4 / 32; ++k) {           // 6 iterations, kept rolled
        const int i = lane + k * 32;
        const float4 w0 = sw[0][i];
        const float4 w1 = sw[1][i];
        const float4 w2 = sw[2][i];
        const float4 w3 = sw[3][i];
        #pragma unroll
        for (int j = 0; j < 4; ++j) {
            const float4 x = r4[(size_t)j * (PH / 4) + i];
            accd[j] += x.x * w0.x + x.y * w0.y + x.z * w0.z + x.w * w0.w;
            acce[j] += x.x * w1.x + x.y * w1.y + x.z * w1.z + x.w * w1.w;
            acca[j] += x.x * w2.x + x.y * w2.y + x.z * w2.z + x.w * w2.w;
            accc[j] += x.x * w3.x + x.y * w3.y + x.z * w3.z + x.w * w3.w;
        }
    }

    // Merged reduction: 4 values -> 1 register in 6 shuffles per token.
    // Afterwards lane%4 holds: 0->d, 1->e, 2->a, 3->c (full warp sums).
    const unsigned full = 0xFFFFFFFFu;
    #pragma unroll
    for (int j = 0; j < 4; ++j) {
        const float t01 = (lane & 1) ? accd[j] : acce[j];
        const float m01 = ((lane & 1) ? acce[j] : accd[j]) + __shfl_xor_sync(full, t01, 1);
        const float t23 = (lane & 1) ? acca[j] : accc[j];
        const float m23 = ((lane & 1) ? accc[j] : acca[j]) + __shfl_xor_sync(full, t23, 1);
        const float tm  = (lane & 2) ? m01 : m23;
        float z = ((lane & 2) ? m23 : m01) + __shfl_xor_sync(full, tm, 2);
        z += __shfl_xor_sync(full, z, 4);
        z += __shfl_xor_sync(full, z, 8);
        z += __shfl_xor_sync(full, z, 16);

        const int tj = t0 + j;
        if (lane == 0) g_sc[tj] = (unsigned char)((mask[tj] != 0) && (z + bsd >= 0.f));
        if (lane == 1) g_ec[tj] = (unsigned char)((mask[tj] != 0) && (z + bed >= 0.f));
        if (lane == 2) g_a[tj]  = z + bm;
        if (lane == 3) g_c[tj]  = z;
    }
}

// ---------------------------------------------------------------------------
// Kernel 2 (measured 22.4us five times, verbatim): span materialization with
// register-cached c-row + streaming stores. One block per (b, 16-row tile);
// each thread owns a fixed 4-wide e-slice reused across the 16 s-rows.
// ---------------------------------------------------------------------------
#define ROWS_PER_BLK 16
__global__ void __launch_bounds__(256) span_kernel(float* __restrict__ out)
{
    const int b    = blockIdx.x >> 5;                 // / (S/ROWS_PER_BLK) = /32
    const int s0   = (blockIdx.x & 31) * ROWS_PER_BLK;
    const int half = threadIdx.x >> 7;                // 0/1: which row of the pair
    const int e0   = (threadIdx.x & 127) << 2;        // fixed 4-wide e-slice

    const float4 c4  = *reinterpret_cast<const float4*>(g_c  + (b << 9) + e0);
    const uchar4 ec4 = *reinterpret_cast<const uchar4*>(g_ec + (b << 9) + e0);
    const float ecx = ec4.x ? 1.f : 0.f;
    const float ecy = ec4.y ? 1.f : 0.f;
    const float ecz = ec4.z ? 1.f : 0.f;
    const float ecw = ec4.w ? 1.f : 0.f;

    #pragma unroll
    for (int r = half; r < ROWS_PER_BLK; r += 2) {
        const int s  = s0 + r;
        const int bs = (b << 9) + s;
        const float a  = g_a[bs];
        const float sc = g_sc[bs] ? 1.f : 0.f;

        float4 sv;
        sv.x = a + c4.x;
        sv.y = a + c4.y;
        sv.z = a + c4.z;
        sv.w = a + c4.w;

        float4 mv;
        mv.x = (e0 + 0 >= s && sv.x > 0.f) ? sc * ecx : 0.f;
        mv.y = (e0 + 1 >= s && sv.y > 0.f) ? sc * ecy : 0.f;
        mv.z = (e0 + 2 >= s && sv.z > 0.f) ? sc * ecz : 0.f;
        mv.w = (e0 + 3 >= s && sv.w > 0.f) ? sc * ecw : 0.f;

        const size_t off = (size_t)bs * PS + e0;
        __stcs(reinterpret_cast<float4*>(out + off),        mv);   // span_mask
        __stcs(reinterpret_cast<float4*>(out + SPAN + off), sv);   // scores
    }
}

// Trailing no-op: keeps the per-replay pattern at 3 launches so ncu's capture
// slot (absolute stream position 5; 2 harness launches precede) lands on
// token_kernel again.
__global__ void dummy_kernel() {}

// ---------------------------------------------------------------------------
extern "C" void kernel_launch(void* const* d_in, const int* in_sizes, int n_in,
                              void* d_out, int out_size)
{
    const float* rep     = (const float*)d_in[0];   // [B,S,H] fp32
    const int*   mask    = (const int*)  d_in[1];   // [B,S]  int32
    const float* W_start = (const float*)d_in[2];   // [H,2]
    const float* b_start = (const float*)d_in[3];   // [2]
    const float* W_end   = (const float*)d_in[4];   // [H,2]
    const float* b_end   = (const float*)d_in[5];   // [2]
    const float* W_m     = (const float*)d_in[6];   // [2H]
    const float* b_m     = (const float*)d_in[7];   // scalar
    float* out = (float*)d_out;                     // [mask | scores], each B*S*S fp32

    // Kernel 1: 8 warps x 4 tokens = 32 tokens per block -> 1024 blocks
    token_kernel<<<NTOK / 32, 256>>>(rep, mask, W_start, b_start, W_end, b_end, W_m, b_m);

    // Kernel 2: 64 batches x 32 row-tiles = 2048 blocks x 256 threads
    span_kernel<<<PB * (PS / ROWS_PER_BLK), 256>>>(out);

    // Pad pattern to 3 launches so ncu keeps capturing token_kernel.
    dummy_kernel<<<1, 32>>>();
}

// round 11
// speedup vs baseline: 1.0695x; 1.0695x over previous
#include <cuda_runtime.h>
#include <cstdint>

// Problem constants (fixed by the reference: B=64, S=512, H=768)
#define PB 64
#define PS 512
#define PH 768
#define NTOK (PB * PS)                       // 32768 tokens
#define SPAN ((size_t)PB * PS * PS)          // 16,777,216 elements per output tensor

// Per-token scratch (device globals: allocation-free, graph-capturable)
__device__ float         g_a[NTOK];
__device__ float         g_c[NTOK];
__device__ unsigned char g_sc[NTOK];
__device__ unsigned char g_ec[NTOK];

// ---------------------------------------------------------------------------
// Kernel 1: per-token fused matvecs, 4 tokens/warp + SOFTWARE-PIPELINED loads.
// R10 ncu: L1 74->31% (LDS sharing worked) but DRAM stuck at 45%, occ 41.7%,
// issue 30% => latency-bound: the rolled loop consumed its 4 LDG.128
// immediately. Double-buffering the rep loads keeps 8 LDG.128 in flight per
// warp (1.8x MLP/SM at 3 blocks/SM), hiding DRAM latency.
// ---------------------------------------------------------------------------
__global__ __launch_bounds__(256) void token_kernel(
    const float* __restrict__ rep,
    const int*   __restrict__ mask,
    const float* __restrict__ W_start,
    const float* __restrict__ b_start,
    const float* __restrict__ W_end,
    const float* __restrict__ b_end,
    const float* __restrict__ W_m,
    const float* __restrict__ b_m)
{
    __shared__ float4 sw[4][PH / 4];   // 12 KB: 4 combined weight vectors

    const int tid = threadIdx.x;

    // Stage combined weights into shared (once per block)
    for (int i = tid; i < PH; i += blockDim.x) {
        reinterpret_cast<float*>(sw[0])[i] = W_start[i * 2 + 1] - W_start[i * 2 + 0];
        reinterpret_cast<float*>(sw[1])[i] = W_end[i * 2 + 1]   - W_end[i * 2 + 0];
        reinterpret_cast<float*>(sw[2])[i] = W_m[i];
        reinterpret_cast<float*>(sw[3])[i] = W_m[PH + i];
    }
    __syncthreads();

    const int warp = tid >> 5;
    const int lane = tid & 31;
    const int t0   = (blockIdx.x * 8 + warp) * 4;     // 4 consecutive tokens

    const float bsd = b_start[1] - b_start[0];
    const float bed = b_end[1]   - b_end[0];
    const float bm  = b_m[0];

    const float4* r4 = reinterpret_cast<const float4*>(rep) + (size_t)t0 * (PH / 4);

    float accd[4] = {0.f, 0.f, 0.f, 0.f};
    float acce[4] = {0.f, 0.f, 0.f, 0.f};
    float acca[4] = {0.f, 0.f, 0.f, 0.f};
    float accc[4] = {0.f, 0.f, 0.f, 0.f};

    // Prime the pipeline: iteration 0's loads.
    float4 x[4];
    #pragma unroll
    for (int j = 0; j < 4; ++j) x[j] = r4[(size_t)j * (PH / 4) + lane];

    #pragma unroll 1
    for (int k = 0; k < PH / 4 / 32; ++k) {           // 6 iterations, rolled
        const int i = lane + k * 32;

        // Prefetch next iteration's rep data before consuming this one's.
        float4 xn[4];
        if (k < PH / 4 / 32 - 1) {
            #pragma unroll
            for (int j = 0; j < 4; ++j) xn[j] = r4[(size_t)j * (PH / 4) + i + 32];
        }

        const float4 w0 = sw[0][i];
        const float4 w1 = sw[1][i];
        const float4 w2 = sw[2][i];
        const float4 w3 = sw[3][i];
        #pragma unroll
        for (int j = 0; j < 4; ++j) {
            accd[j] += x[j].x * w0.x + x[j].y * w0.y + x[j].z * w0.z + x[j].w * w0.w;
            acce[j] += x[j].x * w1.x + x[j].y * w1.y + x[j].z * w1.z + x[j].w * w1.w;
            acca[j] += x[j].x * w2.x + x[j].y * w2.y + x[j].z * w2.z + x[j].w * w2.w;
            accc[j] += x[j].x * w3.x + x[j].y * w3.y + x[j].z * w3.z + x[j].w * w3.w;
        }
        #pragma unroll
        for (int j = 0; j < 4; ++j) x[j] = xn[j];
    }

    // Merged reduction: 6 shuffles per token; lane%4 -> {d,e,a,c}.
    const unsigned full = 0xFFFFFFFFu;
    #pragma unroll
    for (int j = 0; j < 4; ++j) {
        const float t01 = (lane & 1) ? accd[j] : acce[j];
        const float m01 = ((lane & 1) ? acce[j] : accd[j]) + __shfl_xor_sync(full, t01, 1);
        const float t23 = (lane & 1) ? acca[j] : accc[j];
        const float m23 = ((lane & 1) ? accc[j] : acca[j]) + __shfl_xor_sync(full, t23, 1);
        const float tm  = (lane & 2) ? m01 : m23;
        float z = ((lane & 2) ? m23 : m01) + __shfl_xor_sync(full, tm, 2);
        z += __shfl_xor_sync(full, z, 4);
        z += __shfl_xor_sync(full, z, 8);
        z += __shfl_xor_sync(full, z, 16);

        const int tj = t0 + j;
        if (lane == 0) g_sc[tj] = (unsigned char)((mask[tj] != 0) && (z + bsd >= 0.f));
        if (lane == 1) g_ec[tj] = (unsigned char)((mask[tj] != 0) && (z + bed >= 0.f));
        if (lane == 2) g_a[tj]  = z + bm;
        if (lane == 3) g_c[tj]  = z;
    }
}

// ---------------------------------------------------------------------------
// Kernel 2 (measured 22.4us five times, verbatim): span materialization with
// register-cached c-row + streaming stores. One block per (b, 16-row tile);
// each thread owns a fixed 4-wide e-slice reused across the 16 s-rows.
// ---------------------------------------------------------------------------
#define ROWS_PER_BLK 16
__global__ void __launch_bounds__(256) span_kernel(float* __restrict__ out)
{
    const int b    = blockIdx.x >> 5;                 // / (S/ROWS_PER_BLK) = /32
    const int s0   = (blockIdx.x & 31) * ROWS_PER_BLK;
    const int half = threadIdx.x >> 7;                // 0/1: which row of the pair
    const int e0   = (threadIdx.x & 127) << 2;        // fixed 4-wide e-slice

    const float4 c4  = *reinterpret_cast<const float4*>(g_c  + (b << 9) + e0);
    const uchar4 ec4 = *reinterpret_cast<const uchar4*>(g_ec + (b << 9) + e0);
    const float ecx = ec4.x ? 1.f : 0.f;
    const float ecy = ec4.y ? 1.f : 0.f;
    const float ecz = ec4.z ? 1.f : 0.f;
    const float ecw = ec4.w ? 1.f : 0.f;

    #pragma unroll
    for (int r = half; r < ROWS_PER_BLK; r += 2) {
        const int s  = s0 + r;
        const int bs = (b << 9) + s;
        const float a  = g_a[bs];
        const float sc = g_sc[bs] ? 1.f : 0.f;

        float4 sv;
        sv.x = a + c4.x;
        sv.y = a + c4.y;
        sv.z = a + c4.z;
        sv.w = a + c4.w;

        float4 mv;
        mv.x = (e0 + 0 >= s && sv.x > 0.f) ? sc * ecx : 0.f;
        mv.y = (e0 + 1 >= s && sv.y > 0.f) ? sc * ecy : 0.f;
        mv.z = (e0 + 2 >= s && sv.z > 0.f) ? sc * ecz : 0.f;
        mv.w = (e0 + 3 >= s && sv.w > 0.f) ? sc * ecw : 0.f;

        const size_t off = (size_t)bs * PS + e0;
        __stcs(reinterpret_cast<float4*>(out + off),        mv);   // span_mask
        __stcs(reinterpret_cast<float4*>(out + SPAN + off), sv);   // scores
    }
}

// Trailing no-op: keeps the per-replay pattern at 3 launches so ncu's capture
// slot (absolute stream position 5; 2 harness launches precede) lands on
// token_kernel. Will be removed once token tuning converges (~2-3us overhead).
__global__ void dummy_kernel() {}

// ---------------------------------------------------------------------------
extern "C" void kernel_launch(void* const* d_in, const int* in_sizes, int n_in,
                              void* d_out, int out_size)
{
    const float* rep     = (const float*)d_in[0];   // [B,S,H] fp32
    const int*   mask    = (const int*)  d_in[1];   // [B,S]  int32
    const float* W_start = (const float*)d_in[2];   // [H,2]
    const float* b_start = (const float*)d_in[3];   // [2]
    const float* W_end   = (const float*)d_in[4];   // [H,2]
    const float* b_end   = (const float*)d_in[5];   // [2]
    const float* W_m     = (const float*)d_in[6];   // [2H]
    const float* b_m     = (const float*)d_in[7];   // scalar
    float* out = (float*)d_out;                     // [mask | scores], each B*S*S fp32

    // Kernel 1: 8 warps x 4 tokens = 32 tokens per block -> 1024 blocks
    token_kernel<<<NTOK / 32, 256>>>(rep, mask, W_start, b_start, W_end, b_end, W_m, b_m);

    // Kernel 2: 64 batches x 32 row-tiles = 2048 blocks x 256 threads
    span_kernel<<<PB * (PS / ROWS_PER_BLK), 256>>>(out);

    // Pad pattern to 3 launches so ncu keeps capturing token_kernel.
    dummy_kernel<<<1, 32>>>();
}

// round 12
// speedup vs baseline: 1.1056x; 1.0338x over previous
#include <cuda_runtime.h>
#include <cstdint>

// Problem constants (fixed by the reference: B=64, S=512, H=768)
#define PB 64
#define PS 512
#define PH 768
#define NTOK (PB * PS)                       // 32768 tokens
#define SPAN ((size_t)PB * PS * PS)          // 16,777,216 elements per output tensor

// Per-token scratch (device globals: allocation-free, graph-capturable)
__device__ float         g_a[NTOK];
__device__ float         g_c[NTOK];
__device__ unsigned char g_sc[NTOK];
__device__ unsigned char g_ec[NTOK];

// ---------------------------------------------------------------------------
// Kernel 1 (R11 verbatim, measured 25.7us): per-token fused matvecs,
// 4 tokens/warp + software-pipelined rep loads (8 LDG.128 in flight/warp).
// Weight LDS shared across 4 tokens (L1 31%), merged 6-shuffle reduction.
// ---------------------------------------------------------------------------
__global__ __launch_bounds__(256) void token_kernel(
    const float* __restrict__ rep,
    const int*   __restrict__ mask,
    const float* __restrict__ W_start,
    const float* __restrict__ b_start,
    const float* __restrict__ W_end,
    const float* __restrict__ b_end,
    const float* __restrict__ W_m,
    const float* __restrict__ b_m)
{
    __shared__ float4 sw[4][PH / 4];   // 12 KB: 4 combined weight vectors

    const int tid = threadIdx.x;

    // Stage combined weights into shared (once per block)
    for (int i = tid; i < PH; i += blockDim.x) {
        reinterpret_cast<float*>(sw[0])[i] = W_start[i * 2 + 1] - W_start[i * 2 + 0];
        reinterpret_cast<float*>(sw[1])[i] = W_end[i * 2 + 1]   - W_end[i * 2 + 0];
        reinterpret_cast<float*>(sw[2])[i] = W_m[i];
        reinterpret_cast<float*>(sw[3])[i] = W_m[PH + i];
    }
    __syncthreads();

    const int warp = tid >> 5;
    const int lane = tid & 31;
    const int t0   = (blockIdx.x * 8 + warp) * 4;     // 4 consecutive tokens

    const float bsd = b_start[1] - b_start[0];
    const float bed = b_end[1]   - b_end[0];
    const float bm  = b_m[0];

    const float4* r4 = reinterpret_cast<const float4*>(rep) + (size_t)t0 * (PH / 4);

    float accd[4] = {0.f, 0.f, 0.f, 0.f};
    float acce[4] = {0.f, 0.f, 0.f, 0.f};
    float acca[4] = {0.f, 0.f, 0.f, 0.f};
    float accc[4] = {0.f, 0.f, 0.f, 0.f};

    // Prime the pipeline: iteration 0's loads.
    float4 x[4];
    #pragma unroll
    for (int j = 0; j < 4; ++j) x[j] = r4[(size_t)j * (PH / 4) + lane];

    #pragma unroll 1
    for (int k = 0; k < PH / 4 / 32; ++k) {           // 6 iterations, rolled
        const int i = lane + k * 32;

        // Prefetch next iteration's rep data before consuming this one's.
        float4 xn[4];
        if (k < PH / 4 / 32 - 1) {
            #pragma unroll
            for (int j = 0; j < 4; ++j) xn[j] = r4[(size_t)j * (PH / 4) + i + 32];
        }

        const float4 w0 = sw[0][i];
        const float4 w1 = sw[1][i];
        const float4 w2 = sw[2][i];
        const float4 w3 = sw[3][i];
        #pragma unroll
        for (int j = 0; j < 4; ++j) {
            accd[j] += x[j].x * w0.x + x[j].y * w0.y + x[j].z * w0.z + x[j].w * w0.w;
            acce[j] += x[j].x * w1.x + x[j].y * w1.y + x[j].z * w1.z + x[j].w * w1.w;
            acca[j] += x[j].x * w2.x + x[j].y * w2.y + x[j].z * w2.z + x[j].w * w2.w;
            accc[j] += x[j].x * w3.x + x[j].y * w3.y + x[j].z * w3.z + x[j].w * w3.w;
        }
        #pragma unroll
        for (int j = 0; j < 4; ++j) x[j] = xn[j];
    }

    // Merged reduction: 6 shuffles per token; lane%4 -> {d,e,a,c}.
    const unsigned full = 0xFFFFFFFFu;
    #pragma unroll
    for (int j = 0; j < 4; ++j) {
        const float t01 = (lane & 1) ? accd[j] : acce[j];
        const float m01 = ((lane & 1) ? acce[j] : accd[j]) + __shfl_xor_sync(full, t01, 1);
        const float t23 = (lane & 1) ? acca[j] : accc[j];
        const float m23 = ((lane & 1) ? accc[j] : acca[j]) + __shfl_xor_sync(full, t23, 1);
        const float tm  = (lane & 2) ? m01 : m23;
        float z = ((lane & 2) ? m23 : m01) + __shfl_xor_sync(full, tm, 2);
        z += __shfl_xor_sync(full, z, 4);
        z += __shfl_xor_sync(full, z, 8);
        z += __shfl_xor_sync(full, z, 16);

        const int tj = t0 + j;
        if (lane == 0) g_sc[tj] = (unsigned char)((mask[tj] != 0) && (z + bsd >= 0.f));
        if (lane == 1) g_ec[tj] = (unsigned char)((mask[tj] != 0) && (z + bed >= 0.f));
        if (lane == 2) g_a[tj]  = z + bm;
        if (lane == 3) g_c[tj]  = z;
    }
}

// ---------------------------------------------------------------------------
// Kernel 2 (measured 22.4us five times, verbatim): span materialization with
// register-cached c-row + streaming stores. One block per (b, 16-row tile);
// each thread owns a fixed 4-wide e-slice reused across the 16 s-rows.
// ---------------------------------------------------------------------------
#define ROWS_PER_BLK 16
__global__ void __launch_bounds__(256) span_kernel(float* __restrict__ out)
{
    const int b    = blockIdx.x >> 5;                 // / (S/ROWS_PER_BLK) = /32
    const int s0   = (blockIdx.x & 31) * ROWS_PER_BLK;
    const int half = threadIdx.x >> 7;                // 0/1: which row of the pair
    const int e0   = (threadIdx.x & 127) << 2;        // fixed 4-wide e-slice

    const float4 c4  = *reinterpret_cast<const float4*>(g_c  + (b << 9) + e0);
    const uchar4 ec4 = *reinterpret_cast<const uchar4*>(g_ec + (b << 9) + e0);
    const float ecx = ec4.x ? 1.f : 0.f;
    const float ecy = ec4.y ? 1.f : 0.f;
    const float ecz = ec4.z ? 1.f : 0.f;
    const float ecw = ec4.w ? 1.f : 0.f;

    #pragma unroll
    for (int r = half; r < ROWS_PER_BLK; r += 2) {
        const int s  = s0 + r;
        const int bs = (b << 9) + s;
        const float a  = g_a[bs];
        const float sc = g_sc[bs] ? 1.f : 0.f;

        float4 sv;
        sv.x = a + c4.x;
        sv.y = a + c4.y;
        sv.z = a + c4.z;
        sv.w = a + c4.w;

        float4 mv;
        mv.x = (e0 + 0 >= s && sv.x > 0.f) ? sc * ecx : 0.f;
        mv.y = (e0 + 1 >= s && sv.y > 0.f) ? sc * ecy : 0.f;
        mv.z = (e0 + 2 >= s && sv.z > 0.f) ? sc * ecz : 0.f;
        mv.w = (e0 + 3 >= s && sv.w > 0.f) ? sc * ecw : 0.f;

        const size_t off = (size_t)bs * PS + e0;
        __stcs(reinterpret_cast<float4*>(out + off),        mv);   // span_mask
        __stcs(reinterpret_cast<float4*>(out + SPAN + off), sv);   // scores
    }
}

// ---------------------------------------------------------------------------
extern "C" void kernel_launch(void* const* d_in, const int* in_sizes, int n_in,
                              void* d_out, int out_size)
{
    const float* rep     = (const float*)d_in[0];   // [B,S,H] fp32
    const int*   mask    = (const int*)  d_in[1];   // [B,S]  int32
    const float* W_start = (const float*)d_in[2];   // [H,2]
    const float* b_start = (const float*)d_in[3];   // [2]
    const float* W_end   = (const float*)d_in[4];   // [H,2]
    const float* b_end   = (const float*)d_in[5];   // [2]
    const float* W_m     = (const float*)d_in[6];   // [2H]
    const float* b_m     = (const float*)d_in[7];   // scalar
    float* out = (float*)d_out;                     // [mask | scores], each B*S*S fp32

    // Kernel 1: 8 warps x 4 tokens = 32 tokens per block -> 1024 blocks
    token_kernel<<<NTOK / 32, 256>>>(rep, mask, W_start, b_start, W_end, b_end, W_m, b_m);

    // Kernel 2: 64 batches x 32 row-tiles = 2048 blocks x 256 threads
    span_kernel<<<PB * (PS / ROWS_PER_BLK), 256>>>(out);
}